// round 6
// baseline (speedup 1.0000x reference)
#include <cuda_runtime.h>

#define NN 8192
#define FF 128
#define EE 262144
#define METAL 64
#define NOUT 17
#define TWO_N (2*NN)
#define TPB 256
#define GCNB 148                       // GCN blocks (one per SM, all co-resident)
#define JT 512                         // j-tile size for GEMM
#define NTILES (NN / JT)               // 16
#define ROWS_PER_BLOCK 32
#define ROWS_PER_WARP 4
#define GEMMB (TWO_N / ROWS_PER_BLOCK) // 512
#define GRID_TOT (GCNB + GEMMB)        // 660
#define GCN_NT (GCNB * TPB)            // 37888 threads in GCN role

// ---- scratch (device globals: no allocation allowed) ----
__device__ float d_deg[TWO_N];
__device__ float d_dinv[TWO_N];
__device__ float d_gv[4][TWO_N];
__device__ float d_yv[4][TWO_N];
__device__ float d_wc[FF];
__device__ float d_c[4];
__device__ float d_G[TWO_N * NOUT];    // G = Wi @ Wf[:NN]  (16384 x 17)
__device__ unsigned bar_ctr = 0;
__device__ unsigned bar_epoch = 0;

// ---- grid barrier over the GCNB GCN blocks only (replay-safe: epoch grows) ----
__device__ __forceinline__ void gbar() {
    __syncthreads();
    if (threadIdx.x == 0) {
        __threadfence();
        unsigned e = *(volatile unsigned*)&bar_epoch;
        __threadfence();
        if (atomicAdd(&bar_ctr, 1) == GCNB - 1) {
            bar_ctr = 0;
            __threadfence();
            atomicAdd(&bar_epoch, 1);
        } else {
            while (*(volatile unsigned*)&bar_epoch == e) __nanosleep(64);
        }
        __threadfence();
    }
    __syncthreads();
}

// ---- packed fp32x2 helpers (sm_103a FFMA2) ----
__device__ __forceinline__ void ffma2(unsigned long long& acc,
                                      unsigned long long a, unsigned long long b) {
    asm("fma.rn.f32x2 %0, %1, %2, %0;" : "+l"(acc) : "l"(a), "l"(b));
}
__device__ __forceinline__ unsigned long long bcast2(float x) {
    unsigned long long r; unsigned xi = __float_as_uint(x);
    asm("mov.b64 %0, {%1, %1};" : "=l"(r) : "r"(xi));
    return r;
}
__device__ __forceinline__ float2 unpack2(unsigned long long v) {
    unsigned lo, hi;
    asm("mov.b64 {%0, %1}, %2;" : "=r"(lo), "=r"(hi) : "l"(v));
    return make_float2(__uint_as_float(lo), __uint_as_float(hi));
}

// ---------------- pre: deg=1, out init (bf + meta@Wf), combined weights ----------------
__global__ void k_pre(const float* __restrict__ W1, const float* __restrict__ b1,
                      const float* __restrict__ W2, const float* __restrict__ b2,
                      const float* __restrict__ W3, const float* __restrict__ b3,
                      const float* __restrict__ W4, const float* __restrict__ b4,
                      const float* __restrict__ meta, const float* __restrict__ Wf,
                      const float* __restrict__ bf, float* __restrict__ out) {
    int tid = blockIdx.x * blockDim.x + threadIdx.x;
    for (int i = tid; i < TWO_N; i += gridDim.x * blockDim.x) d_deg[i] = 1.0f;
    if (blockIdx.x == 0 && threadIdx.x < NOUT) {
        int j = threadIdx.x;
        float s = bf[j];
#pragma unroll 8
        for (int m = 0; m < METAL; m++)
            s += meta[m] * Wf[(size_t)(NN + m) * NOUT + j];
        out[j] = s;
    }
    if (blockIdx.x == 1 && threadIdx.x < FF) {
        int f = threadIdx.x;
        float w34[4], w234[8];
#pragma unroll
        for (int c = 0; c < 4; c++)
            w34[c] = W3[c * 2 + 0] * W4[0] + W3[c * 2 + 1] * W4[1];
#pragma unroll
        for (int r = 0; r < 8; r++) {
            float s = 0.0f;
#pragma unroll
            for (int c = 0; c < 4; c++) s += W2[r * 4 + c] * w34[c];
            w234[r] = s;
        }
        float s = 0.0f;
#pragma unroll
        for (int r = 0; r < 8; r++) s += W1[f * 8 + r] * w234[r];
        d_wc[f] = s;
        if (f == 0) {
            float c1 = 0.0f, c2 = 0.0f;
#pragma unroll
            for (int r = 0; r < 8; r++) c1 += b1[r] * w234[r];
#pragma unroll
            for (int c = 0; c < 4; c++) c2 += b2[c] * w34[c];
            d_c[0] = c1;
            d_c[1] = c2;
            d_c[2] = b3[0] * W4[0] + b3[1] * W4[1];
            d_c[3] = b4[0];
        }
    }
}

// ================== fused kernel: GCN pipeline (blocks 0..147) || G-GEMM (rest) ==================
__global__ void __launch_bounds__(TPB, 2) k_fused(
    const float* __restrict__ x1, const float* __restrict__ x2,
    const int* __restrict__ ei1, const int* __restrict__ ei2,
    const float* __restrict__ Wi, const float* __restrict__ Wf)
{
    __shared__ float s_wf[JT * 20];   // 40 KB (GCN role reuses first 128 floats)

    if (blockIdx.x < GCNB) {
        // ======================= GCN role =======================
        const int tid = blockIdx.x * TPB + threadIdx.x;
        const int Q = EE / 4;

        // phase: degree count (self-loop preset in k_pre)
        for (int t = tid; t < 2 * Q; t += GCN_NT) {
            int4 dd; int off;
            if (t < Q) { dd = ((const int4*)(ei1 + EE))[t];     off = 0;  }
            else       { dd = ((const int4*)(ei2 + EE))[t - Q]; off = NN; }
            atomicAdd(&d_deg[off + dd.x], 1.0f);
            atomicAdd(&d_deg[off + dd.y], 1.0f);
            atomicAdd(&d_deg[off + dd.z], 1.0f);
            atomicAdd(&d_deg[off + dd.w], 1.0f);
        }
        gbar();

        // phase: dinv + g0 = dinv*(x@wc)  (warp per node)
        if (threadIdx.x < FF) s_wf[threadIdx.x] = d_wc[threadIdx.x];
        __syncthreads();
        {
            const int w = tid >> 5, lane = tid & 31, NW = GCN_NT >> 5;
            float4 wv = ((const float4*)s_wf)[lane];
            for (int i = w; i < TWO_N; i += NW) {
                const float* x = (i < NN) ? (x1 + (size_t)i * FF)
                                          : (x2 + (size_t)(i - NN) * FF);
                float4 v = ((const float4*)x)[lane];
                float s = v.x * wv.x + v.y * wv.y + v.z * wv.z + v.w * wv.w;
#pragma unroll
                for (int o = 16; o > 0; o >>= 1) s += __shfl_xor_sync(0xffffffff, s, o);
                if (lane == 0) {
                    float dv = rsqrtf(d_deg[i]);
                    d_dinv[i] = dv;
                    float g = dv * s;
                    d_gv[0][i] = g;
                    d_yv[0][i] = g;
                }
            }
        }
        gbar();

        // 4 propagation rounds
        for (int r = 0; r < 4; r++) {
            const float* gsrc = d_gv[r];
            float*       ydst = d_yv[r];
            for (int t = tid; t < 2 * Q; t += GCN_NT) {
                int4 s4, d4; int off;
                if (t < Q) {
                    s4 = ((const int4*)ei1)[t];     d4 = ((const int4*)(ei1 + EE))[t];     off = 0;
                } else {
                    s4 = ((const int4*)ei2)[t - Q]; d4 = ((const int4*)(ei2 + EE))[t - Q]; off = NN;
                }
                float g0 = gsrc[off + s4.x];
                float g1 = gsrc[off + s4.y];
                float g2 = gsrc[off + s4.z];
                float g3 = gsrc[off + s4.w];
                atomicAdd(&ydst[off + d4.x], g0);
                atomicAdd(&ydst[off + d4.y], g1);
                atomicAdd(&ydst[off + d4.z], g2);
                atomicAdd(&ydst[off + d4.w], g3);
            }
            if (r < 3) {
                gbar();
                float cr = d_c[r];
                for (int i = tid; i < TWO_N; i += GCN_NT) {
                    float dv = d_dinv[i];
                    float g = dv * (dv * d_yv[r][i] + cr);
                    d_gv[r + 1][i] = g;
                    d_yv[r + 1][i] = g;
                }
                gbar();
            }
            // r==3: y3 consumed by k_final (next launch)
        }
    } else {
        // ======================= GEMM role: G = Wi @ Wf[:NN] =======================
        const int gb = blockIdx.x - GCNB;            // 0..511
        const int w = threadIdx.x >> 5, lane = threadIdx.x & 31;
        const int r0 = gb * ROWS_PER_BLOCK + w * ROWS_PER_WARP;   // 4 rows/warp
        const float4* Wi4 = (const float4*)Wi;

        unsigned long long acc[ROWS_PER_WARP][9];
#pragma unroll
        for (int i = 0; i < ROWS_PER_WARP; i++)
#pragma unroll
            for (int p = 0; p < 9; p++) acc[i][p] = 0ull;

        for (int t = 0; t < NTILES; t++) {
            __syncthreads();
            // stage Wf tile [JT][17] into smem padded to 20 floats/row
            for (int idx = threadIdx.x; idx < JT * NOUT; idx += TPB) {
                int j = idx / NOUT, o = idx - j * NOUT;
                s_wf[j * 20 + o] = Wf[(size_t)(t * JT + j) * NOUT + o];
            }
            for (int idx = threadIdx.x; idx < JT; idx += TPB)
                s_wf[idx * 20 + 17] = 0.0f;      // pad for pair 8
            __syncthreads();

            // 4 quad-iters: each lane handles 4 consecutive j per iter
#pragma unroll
            for (int q = 0; q < 4; q++) {
                const int j0 = q * 128 + lane * 4;
                float4 m4[ROWS_PER_WARP];
#pragma unroll
                for (int i = 0; i < ROWS_PER_WARP; i++)
                    m4[i] = __ldcs(&Wi4[(size_t)(r0 + i) * (NN / 4) + t * (JT / 4) + (j0 >> 2)]);
#pragma unroll
                for (int jj = 0; jj < 4; jj++) {
                    const unsigned long long* wfp =
                        (const unsigned long long*)&s_wf[(j0 + jj) * 20];
                    unsigned long long wf2[9];
#pragma unroll
                    for (int p = 0; p < 9; p++) wf2[p] = wfp[p];
#pragma unroll
                    for (int i = 0; i < ROWS_PER_WARP; i++) {
                        const float* mf = (const float*)&m4[i];
                        unsigned long long m2 = bcast2(mf[jj]);
#pragma unroll
                        for (int p = 0; p < 9; p++) ffma2(acc[i][p], m2, wf2[p]);
                    }
                }
            }
        }

        // butterfly-reduce across lanes, lane0 stores exclusive rows (no atomics)
#pragma unroll
        for (int i = 0; i < ROWS_PER_WARP; i++) {
#pragma unroll
            for (int p = 0; p < 9; p++) {
                float2 v = unpack2(acc[i][p]);
#pragma unroll
                for (int o = 16; o > 0; o >>= 1) {
                    v.x += __shfl_xor_sync(0xffffffff, v.x, o);
                    v.y += __shfl_xor_sync(0xffffffff, v.y, o);
                }
                if (lane == 0) {
                    d_G[(size_t)(r0 + i) * NOUT + 2 * p] = v.x;
                    if (2 * p + 1 < NOUT)
                        d_G[(size_t)(r0 + i) * NOUT + 2 * p + 1] = v.y;
                }
            }
        }
    }
}

// ---------------- final: out += sum_k h[k]*G[k][:] + bi @ Wf[:NN] ----------------
__global__ void k_final(const float* __restrict__ Wf, const float* __restrict__ bi,
                        float* __restrict__ out) {
    int k = blockIdx.x * blockDim.x + threadIdx.x;   // exactly TWO_N threads
    float h = d_dinv[k] * d_yv[3][k] + d_c[3];
    float acc[NOUT];
#pragma unroll
    for (int o = 0; o < NOUT; o++) acc[o] = h * d_G[(size_t)k * NOUT + o];
    if (k < NN) {
        float b = bi[k];
#pragma unroll
        for (int o = 0; o < NOUT; o++) acc[o] += b * Wf[(size_t)k * NOUT + o];
    }
#pragma unroll
    for (int o = 0; o < NOUT; o++) {
#pragma unroll
        for (int s = 16; s > 0; s >>= 1)
            acc[o] += __shfl_xor_sync(0xffffffff, acc[o], s);
    }
    if ((threadIdx.x & 31) == 0) {
#pragma unroll
        for (int o = 0; o < NOUT; o++) atomicAdd(&out[o], acc[o]);
    }
}

// ================================================================= launch
extern "C" void kernel_launch(void* const* d_in, const int* in_sizes, int n_in,
                              void* d_out, int out_size) {
    const float* x1   = (const float*)d_in[0];
    const float* x2   = (const float*)d_in[1];
    const float* meta = (const float*)d_in[2];
    const float* W1   = (const float*)d_in[3];
    const float* b1   = (const float*)d_in[4];
    const float* W2   = (const float*)d_in[5];
    const float* b2   = (const float*)d_in[6];
    const float* W3   = (const float*)d_in[7];
    const float* b3   = (const float*)d_in[8];
    const float* W4   = (const float*)d_in[9];
    const float* b4   = (const float*)d_in[10];
    const float* Wi   = (const float*)d_in[11];
    const float* bi   = (const float*)d_in[12];
    const float* Wf   = (const float*)d_in[13];
    const float* bf   = (const float*)d_in[14];
    const int*   ei1  = (const int*)d_in[15];
    const int*   ei2  = (const int*)d_in[16];
    float* out = (float*)d_out;

    k_pre<<<32, TPB>>>(W1, b1, W2, b2, W3, b3, W4, b4, meta, Wf, bf, out);
    k_fused<<<GRID_TOT, TPB>>>(x1, x2, ei1, ei2, Wi, Wf);
    k_final<<<TWO_N / TPB, TPB>>>(Wf, bi, out);
}

// round 7
// speedup vs baseline: 3.2401x; 3.2401x over previous
#include <cuda_runtime.h>

#define NN 8192
#define FF 128
#define EE 262144
#define METAL 64
#define NOUT 17
#define TWO_N (2*NN)
#define TWO_E (2*EE)
#define KSPLIT 128
#define KCHUNK (TWO_N / KSPLIT)   // 128
#define TPB 256

// prefetch geometry: 5 regions x 24MB = 120MB of Wi warmed into L2
#define PF_BLOCKS 64
#define PF_BYTES (24u * 1024u * 1024u)
#define PF_LINES (PF_BYTES / 128u)          // 196608
#define PF_PER_T (PF_LINES / (PF_BLOCKS * TPB))  // 12

// count role: 8 dst-indices per thread
#define QC (EE / 8)                // 32768
#define CNT_BLOCKS ((2 * QC) / TPB) // 256
// scatter role: 8 edges per thread
#define SC_BLOCKS ((2 * QC) / TPB)  // 256

// ---- scratch (device globals: no allocation allowed) ----
__device__ int   d_degi[TWO_N];     // zero at entry; reset by k_xwc each replay
__device__ float d_dinv[TWO_N];
__device__ float d_gv[4][TWO_N];
__device__ float d_yv[4][TWO_N];
__device__ float d_res[NN];         // zero at entry; reset by k_out_acc each replay
__device__ float d_wc[FF];
__device__ float d_c[4];

__device__ __forceinline__ void pf_l2(const char* p) {
    asm volatile("prefetch.global.L2 [%0];" :: "l"(p));
}
__device__ __forceinline__ void pf_region(const float* Wi, int region, int blk) {
    const char* base = (const char*)Wi + (size_t)region * PF_BYTES;
    int t = blk * TPB + threadIdx.x;
#pragma unroll
    for (int i = 0; i < PF_PER_T; i++)
        pf_l2(base + (size_t)(t + i * PF_BLOCKS * TPB) * 128);
}

// ============ head: degree count + combine weights + out init + PF region 4 ============
__global__ void k_head(const int* __restrict__ ei1, const int* __restrict__ ei2,
                       const float* __restrict__ W1, const float* __restrict__ b1,
                       const float* __restrict__ W2, const float* __restrict__ b2,
                       const float* __restrict__ W3, const float* __restrict__ b3,
                       const float* __restrict__ W4, const float* __restrict__ b4,
                       const float* __restrict__ meta, const float* __restrict__ Wf,
                       const float* __restrict__ bf, float* __restrict__ out,
                       const float* __restrict__ Wi) {
    int b = blockIdx.x;
    if (b < CNT_BLOCKS) {
        int t = b * TPB + threadIdx.x;
        int4 a0, a1; int off;
        if (t < QC) { a0 = ((const int4*)(ei1 + EE))[2 * t];
                      a1 = ((const int4*)(ei1 + EE))[2 * t + 1]; off = 0; }
        else        { int u = t - QC;
                      a0 = ((const int4*)(ei2 + EE))[2 * u];
                      a1 = ((const int4*)(ei2 + EE))[2 * u + 1]; off = NN; }
        atomicAdd(&d_degi[off + a0.x], 1); atomicAdd(&d_degi[off + a0.y], 1);
        atomicAdd(&d_degi[off + a0.z], 1); atomicAdd(&d_degi[off + a0.w], 1);
        atomicAdd(&d_degi[off + a1.x], 1); atomicAdd(&d_degi[off + a1.y], 1);
        atomicAdd(&d_degi[off + a1.z], 1); atomicAdd(&d_degi[off + a1.w], 1);
    } else if (b == CNT_BLOCKS) {
        if (threadIdx.x < FF) {
            int f = threadIdx.x;
            float w34[4], w234[8];
#pragma unroll
            for (int c = 0; c < 4; c++)
                w34[c] = W3[c * 2 + 0] * W4[0] + W3[c * 2 + 1] * W4[1];
#pragma unroll
            for (int r = 0; r < 8; r++) {
                float s = 0.0f;
#pragma unroll
                for (int c = 0; c < 4; c++) s += W2[r * 4 + c] * w34[c];
                w234[r] = s;
            }
            float s = 0.0f;
#pragma unroll
            for (int r = 0; r < 8; r++) s += W1[f * 8 + r] * w234[r];
            d_wc[f] = s;
            if (f == 0) {
                float c1 = 0.0f, c2 = 0.0f;
#pragma unroll
                for (int r = 0; r < 8; r++) c1 += b1[r] * w234[r];
#pragma unroll
                for (int c = 0; c < 4; c++) c2 += b2[c] * w34[c];
                d_c[0] = c1;
                d_c[1] = c2;
                d_c[2] = b3[0] * W4[0] + b3[1] * W4[1];
                d_c[3] = b4[0];
            }
        }
    } else if (b == CNT_BLOCKS + 1) {
        if (threadIdx.x < NOUT) {
            int j = threadIdx.x;
            float s = bf[j];
#pragma unroll 8
            for (int m = 0; m < METAL; m++)
                s += meta[m] * Wf[(size_t)(NN + m) * NOUT + j];
            out[j] = s;
        }
    } else {
        pf_region(Wi, 4, b - (CNT_BLOCKS + 2));
    }
}

// ------ g0 = dinv*(x@wc); dinv = rsqrt(degi+1); degi reset (warp per node) ------
__global__ void k_xwc(const float* __restrict__ x1, const float* __restrict__ x2) {
    __shared__ float swc[FF];
    if (threadIdx.x < FF) swc[threadIdx.x] = d_wc[threadIdx.x];
    __syncthreads();
    int gt = blockIdx.x * blockDim.x + threadIdx.x;
    int i = gt >> 5;
    int lane = gt & 31;
    if (i >= TWO_N) return;
    const float* x = (i < NN) ? (x1 + (size_t)i * FF) : (x2 + (size_t)(i - NN) * FF);
    float4 v = ((const float4*)x)[lane];
    float4 w = ((const float4*)swc)[lane];
    float s = v.x * w.x + v.y * w.y + v.z * w.z + v.w * w.w;
#pragma unroll
    for (int o = 16; o > 0; o >>= 1) s += __shfl_xor_sync(0xffffffff, s, o);
    if (lane == 0) {
        int dg = d_degi[i];
        d_degi[i] = 0;                       // reset for next replay
        float dv = rsqrtf((float)(dg + 1));
        d_dinv[i] = dv;
        float g = dv * s;
        d_gv[0][i] = g;
        d_yv[0][i] = g;
    }
}

// -------- scatter round r (8 edges/thread) + PF role (region r) --------
__global__ void k_scat(const int* __restrict__ ei1, const int* __restrict__ ei2,
                       int r, const float* __restrict__ Wi) {
    int b = blockIdx.x;
    if (b >= SC_BLOCKS) { pf_region(Wi, r, b - SC_BLOCKS); return; }
    int t = b * TPB + threadIdx.x;
    const float* g = d_gv[r];
    float* y = d_yv[r];
    int4 s0, s1, dd0, dd1; int off;
    if (t < QC) {
        s0  = ((const int4*)ei1)[2 * t];        s1  = ((const int4*)ei1)[2 * t + 1];
        dd0 = ((const int4*)(ei1 + EE))[2 * t]; dd1 = ((const int4*)(ei1 + EE))[2 * t + 1];
        off = 0;
    } else {
        int u = t - QC;
        s0  = ((const int4*)ei2)[2 * u];        s1  = ((const int4*)ei2)[2 * u + 1];
        dd0 = ((const int4*)(ei2 + EE))[2 * u]; dd1 = ((const int4*)(ei2 + EE))[2 * u + 1];
        off = NN;
    }
    float g0 = g[off + s0.x], g1 = g[off + s0.y], g2 = g[off + s0.z], g3 = g[off + s0.w];
    float g4 = g[off + s1.x], g5 = g[off + s1.y], g6 = g[off + s1.z], g7 = g[off + s1.w];
    atomicAdd(&y[off + dd0.x], g0); atomicAdd(&y[off + dd0.y], g1);
    atomicAdd(&y[off + dd0.z], g2); atomicAdd(&y[off + dd0.w], g3);
    atomicAdd(&y[off + dd1.x], g4); atomicAdd(&y[off + dd1.y], g5);
    atomicAdd(&y[off + dd1.z], g6); atomicAdd(&y[off + dd1.w], g7);
}

// -------------------- node update r: g_{r+1} = y_{r+1} = dv*(dv*y_r + c_r)
__global__ void k_node(int r) {
    int i = blockIdx.x * blockDim.x + threadIdx.x;
    if (i >= TWO_N) return;
    float dv = d_dinv[i];
    float g = dv * (dv * d_yv[r][i] + d_c[r]);
    d_gv[r + 1][i] = g;
    d_yv[r + 1][i] = g;
}

// ---- big GEMV: res[j] += sum_k h[k]*Wi[k*N+j]; h = dinv*y3 + c3 on the fly
__global__ void __launch_bounds__(TPB) k_wi_gemv(const float* __restrict__ Wi) {
    __shared__ float sh[KCHUNK];
    int k0 = blockIdx.y * KCHUNK;
    if (threadIdx.x < KCHUNK) {
        int k = k0 + threadIdx.x;
        sh[threadIdx.x] = d_dinv[k] * d_yv[3][k] + d_c[3];
    }
    __syncthreads();
    int j4 = blockIdx.x * blockDim.x + threadIdx.x;
    const float4* Wi4 = (const float4*)Wi;
    float4 acc = make_float4(0.f, 0.f, 0.f, 0.f);
#pragma unroll 8
    for (int kk = 0; kk < KCHUNK; kk++) {
        float c = sh[kk];
        float4 w = __ldcs(&Wi4[(size_t)(k0 + kk) * (NN / 4) + j4]);
        acc.x += c * w.x; acc.y += c * w.y; acc.z += c * w.z; acc.w += c * w.w;
    }
    int j = j4 * 4;
    atomicAdd(&d_res[j + 0], acc.x);
    atomicAdd(&d_res[j + 1], acc.y);
    atomicAdd(&d_res[j + 2], acc.z);
    atomicAdd(&d_res[j + 3], acc.w);
}

// ---------------- out += (res + bi) @ Wf[:N]; reset res for next replay
__global__ void k_out_acc(const float* __restrict__ Wf,
                          const float* __restrict__ bi,
                          float* __restrict__ out) {
    int i = blockIdx.x * blockDim.x + threadIdx.x;   // exactly NN threads
    float r = d_res[i] + bi[i];
    d_res[i] = 0.0f;                                  // reset for next replay
    float acc[NOUT];
#pragma unroll
    for (int j = 0; j < NOUT; j++) acc[j] = r * Wf[(size_t)i * NOUT + j];
#pragma unroll
    for (int j = 0; j < NOUT; j++) {
#pragma unroll
        for (int o = 16; o > 0; o >>= 1)
            acc[j] += __shfl_xor_sync(0xffffffff, acc[j], o);
    }
    if ((threadIdx.x & 31) == 0) {
#pragma unroll
        for (int j = 0; j < NOUT; j++) atomicAdd(&out[j], acc[j]);
    }
}

// ================================================================= launch
extern "C" void kernel_launch(void* const* d_in, const int* in_sizes, int n_in,
                              void* d_out, int out_size) {
    const float* x1   = (const float*)d_in[0];
    const float* x2   = (const float*)d_in[1];
    const float* meta = (const float*)d_in[2];
    const float* W1   = (const float*)d_in[3];
    const float* b1   = (const float*)d_in[4];
    const float* W2   = (const float*)d_in[5];
    const float* b2   = (const float*)d_in[6];
    const float* W3   = (const float*)d_in[7];
    const float* b3   = (const float*)d_in[8];
    const float* W4   = (const float*)d_in[9];
    const float* b4   = (const float*)d_in[10];
    const float* Wi   = (const float*)d_in[11];
    const float* bi   = (const float*)d_in[12];
    const float* Wf   = (const float*)d_in[13];
    const float* bf   = (const float*)d_in[14];
    const int*   ei1  = (const int*)d_in[15];
    const int*   ei2  = (const int*)d_in[16];
    float* out = (float*)d_out;

    k_head<<<CNT_BLOCKS + 2 + PF_BLOCKS, TPB>>>(ei1, ei2, W1, b1, W2, b2, W3, b3,
                                                W4, b4, meta, Wf, bf, out, Wi);
    k_xwc<<<(TWO_N * 32) / TPB, TPB>>>(x1, x2);
    for (int r = 0; r < 4; r++) {
        k_scat<<<SC_BLOCKS + PF_BLOCKS, TPB>>>(ei1, ei2, r, Wi);
        if (r < 3) k_node<<<TWO_N / TPB, TPB>>>(r);
    }
    {
        dim3 grid(NN / (TPB * 4), KSPLIT);
        k_wi_gemv<<<grid, TPB>>>(Wi);
    }
    k_out_acc<<<NN / TPB, TPB>>>(Wf, bi, out);
}